// round 14
// baseline (speedup 1.0000x reference)
#include <cuda_runtime.h>
#include <cuda_fp16.h>
#include <cstdint>
#include <math.h>

#define NMAX 262144
#define GMAX 8192
#define EDIM 118
#define FDIM 128
#define KTAB 512          // intervals per branch (KTAB+1 grid rows)
#define WPITCH 132        // 16B-aligned rows; conflict-free LDS.128 phases
#define NTABBLK 130
#define NSCANBLK 592

// ---------------- scratch (device globals; no allocation) ----------------
__device__ float  g_y[NMAX];
__device__ float  g_denom[GMAX];
__device__ float  g_dot[EDIM * 2];
__device__ float  g_amax;
__device__ float  g_lin[2 * FDIM];                   // F'(0) per branch
__device__ __half g_tabh[2][KTAB + 1][FDIM];         // residual G(|att|), fp16 rows (256B)

// ---------------- helpers ----------------
__device__ __forceinline__ float s1f(float x) {      // silu(x) - x/2, O(x^2), no cancellation
    return 0.5f * x * tanhf(0.5f * x);
}
__device__ __forceinline__ float dot128v(const float* __restrict__ a,
                                         const float* __restrict__ b) {
    float d0 = 0.f, d1 = 0.f, d2 = 0.f, d3 = 0.f;
#pragma unroll
    for (int k = 0; k < FDIM; k += 8) {
        float4 av0 = *(const float4*)(a + k);
        float4 bv0 = *(const float4*)(b + k);
        float4 av1 = *(const float4*)(a + k + 4);
        float4 bv1 = *(const float4*)(b + k + 4);
        d0 = fmaf(av0.x, bv0.x, d0);
        d1 = fmaf(av0.y, bv0.y, d1);
        d2 = fmaf(av0.z, bv0.z, d2);
        d3 = fmaf(av0.w, bv0.w, d3);
        d0 = fmaf(av1.x, bv1.x, d0);
        d1 = fmaf(av1.y, bv1.y, d1);
        d2 = fmaf(av1.z, bv1.z, d2);
        d3 = fmaf(av1.w, bv1.w, d3);
    }
    return (d0 + d1) + (d2 + d3);
}

// ---------------- kernel: zero denom + amax + dot table ----------------
__global__ void k_prep(const float* __restrict__ Wq, const float* __restrict__ Wk,
                       const float* __restrict__ psi, int G) {
    __shared__ float sk[256];
    __shared__ float smax[8];
    int t = threadIdx.x;
    for (int i = t; i < G; i += 256) g_denom[i] = 0.f;
    sk[t] = Wk[t];
    float m = 0.f;
    for (int i = t; i < G; i += 256) m = fmaxf(m, fabsf(psi[i]));
#pragma unroll
    for (int o = 16; o; o >>= 1) m = fmaxf(m, __shfl_xor_sync(0xffffffffu, m, o));
    if ((t & 31) == 0) smax[t >> 5] = m;
    __syncthreads();
    if (t == 0) {
        float mm = 1e-12f;
        for (int i = 0; i < 8; ++i) mm = fmaxf(mm, smax[i]);
        g_amax = mm;
    }
    if (t < EDIM) {
        float a0 = 0.f, a1 = 0.f;
#pragma unroll 8
        for (int f = 0; f < FDIM; ++f) {
            float w = Wq[f * EDIM + t];
            a0 = fmaf(w, sk[f], a0);
            a1 = fmaf(w, sk[FDIM + f], a1);
        }
        g_dot[t * 2 + 0] = a0;
        g_dot[t * 2 + 1] = a1;
    }
}

// ---------------- fused kernel: tab blocks (0..129) + scan blocks (130..721) --
// Tab:  hlin = W1@wv;  h(a) = 0.5a*hlin + W1@s1(a*wv)
//       F(a) - a*F1 = W2 @ [ 0.5*(W1@s1(a*wv)) + s1(h(a)) ];  F1 = wv + 0.25*(W2@hlin)
// Scan: flat float4 stream over the one-hot matrix, 4x ILP.
extern __shared__ float smf[];

__global__ void __launch_bounds__(512)
k_scantab(const float4* __restrict__ oh4, const float* __restrict__ psi,
          const int* __restrict__ bs, int nvec,
          const float* __restrict__ Wv, const float* __restrict__ W1,
          const float* __restrict__ W2) {
    int t = threadIdx.x;
    if (blockIdx.x < NTABBLK) {
        // ---------------- tab path ----------------
        float* sW  = smf;                      // [128][WPITCH] (W1, then W2)
        float* swv = sW + FDIM * WPITCH;       // [128]
        float* shl = swv + FDIM;               // [128] hlin
        float* sSv = shl + FDIM;               // [8][128] s1(a_u*wv)
        float* sB  = sSv + 8 * FDIM;           // [8][128] bracket
        int b = blockIdx.x;
        int r = (b >= 65) ? 1 : 0;
        int i0 = (b - r * 65) * 8;
        float sgn = r ? -1.f : 1.f;
        bool active = (t < 128);

        const float4* W1v = (const float4*)W1;
        for (int i = t; i < FDIM * 32; i += 512) {      // all 512 threads load W1
            int row = i >> 5, c = (i & 31) * 4;
            *(float4*)(sW + row * WPITCH + c) = W1v[i];
        }
        float wv = 0.f;
        if (active) {
            wv = Wv[r * FDIM + t];
            swv[t] = wv;
        }
        __syncthreads();

        const float* wrow = sW + t * WPITCH;
        float amax = g_amax;
        float hlin = 0.f;
        float av[8];
        if (active) {
            hlin = dot128v(wrow, swv);
            shl[t] = hlin;
#pragma unroll
            for (int u = 0; u < 8; ++u) {
                int i = i0 + u;
                float mag = (i == 0) ? (amax * (1.f / 8192.f))
                                     : (amax * (float)i * (1.f / KTAB));
                av[u] = sgn * mag;
                sSv[u * FDIM + t] = s1f(av[u] * wv);
            }
        }
        __syncthreads();

        if (active) {
#pragma unroll
            for (int u = 0; u < 8; ++u) {
                if (i0 + u > KTAB) break;
                float tt = dot128v(wrow, sSv + u * FDIM);   // W1@s1(a*wv)
                float h = fmaf(0.5f * av[u], hlin, tt);
                sB[u * FDIM + t] = fmaf(0.5f, tt, s1f(h));
            }
        }
        __syncthreads();

        const float4* W2v = (const float4*)W2;
        for (int i = t; i < FDIM * 32; i += 512) {      // all 512 threads load W2
            int row = i >> 5, c = (i & 31) * 4;
            *(float4*)(sW + row * WPITCH + c) = W2v[i];
        }
        __syncthreads();

        if (active) {
            if (i0 == 0) {
                float gl = dot128v(wrow, shl);
                g_lin[r * FDIM + t] = fmaf(0.25f, gl, wv);
            }
#pragma unroll
            for (int u = 0; u < 8; ++u) {
                int i = i0 + u;
                if (i > KTAB) break;
                float resid = dot128v(wrow, sB + u * FDIM);
                g_tabh[r][i][t] = __float2half(resid / (av[u] * av[u]));
            }
        }
    } else {
        // ---------------- scan path ----------------
        int stride = NSCANBLK * 512;
        int start = (blockIdx.x - NTABBLK) * 512 + t;
        for (int base = start; base < nvec; base += 4 * stride) {
            float4 v[4];
            int ii[4];
#pragma unroll
            for (int u = 0; u < 4; ++u) {
                ii[u] = base + u * stride;
                if (ii[u] < nvec) v[u] = __ldcs(oh4 + ii[u]);
                else v[u] = make_float4(0.f, 0.f, 0.f, 0.f);
            }
#pragma unroll
            for (int u = 0; u < 4; ++u) {
                float vv[4] = {v[u].x, v[u].y, v[u].z, v[u].w};
#pragma unroll
                for (int c = 0; c < 4; ++c) {
                    if (vv[c] != 0.f) {
                        unsigned f = 4u * (unsigned)ii[u] + (unsigned)c;
                        unsigned atom = f / 118u;
                        unsigned e = f - atom * 118u;
                        int g = bs[atom];
                        float p = psi[g];
                        int r = (p < 0.f) ? 1 : 0;
                        float qk = g_dot[e * 2 + r] * 0.08838834764831845f; // 1/sqrt(128)
                        float y = (qk > 20.f) ? qk : log1pf(expf(qk));
                        g_y[atom] = y;
                        atomicAdd(&g_denom[g], y);
                    }
                }
            }
        }
    }
}

// ---------------- kernel: persistent fused att + lookup + epilogue ------------
__device__ __forceinline__ float att_gather(const float* __restrict__ psi,
                                            const int* __restrict__ bs,
                                            int n0, int nwarps, int lane, int N) {
    float a = 0.f;
    if (lane < 4) {
        int n = n0 + lane * nwarps;
        if (n < N) {
            int g = __ldg(bs + n);
            float p = __ldg(psi + g);
            a = p * g_y[n] / (g_denom[g] + 1e-6f);
        }
    }
    return a;
}

__global__ void __launch_bounds__(256)
k_out(const float* __restrict__ psi, const int* __restrict__ bs,
      float* __restrict__ out, int N) {
    int lane = threadIdx.x & 31;
    int gw = (blockIdx.x * blockDim.x + threadIdx.x) >> 5;
    int nwarps = (gridDim.x * blockDim.x) >> 5;
    int step = 4 * nwarps;
    // F1 for both branches in registers, loaded once per thread
    float4 f1a = ((const float4*)g_lin)[lane];
    float4 f1b = ((const float4*)(g_lin + FDIM))[lane];
    float scale = (float)KTAB / g_amax;

    int first = gw;
    float a_pref = att_gather(psi, bs, first, nwarps, lane, N);

    for (int n0 = first; n0 < N; n0 += step) {
        float att[4];
#pragma unroll
        for (int u = 0; u < 4; ++u)
            att[u] = __shfl_sync(0xffffffffu, a_pref, u);
        // prefetch next chunk's att (loads overlap current processing)
        float a_next = att_gather(psi, bs, n0 + step, nwarps, lane, N);

        uint2 raw[4];
        int nn[4];
#pragma unroll
        for (int u = 0; u < 4; ++u) {
            nn[u] = n0 + u * nwarps;
            int r = (att[u] < 0.f) ? 1 : 0;
            int j = __float2int_rn(fabsf(att[u]) * scale);
            if (j > KTAB) j = KTAB;
            raw[u] = (nn[u] < N) ? __ldg((const uint2*)(&g_tabh[r][j][0]) + lane)
                                 : make_uint2(0u, 0u);
        }
#pragma unroll
        for (int u = 0; u < 4; ++u) {
            if (nn[u] < N) {
                float2 a01 = __half22float2(*(const __half2*)&raw[u].x);
                float2 a23 = __half22float2(*(const __half2*)&raw[u].y);
                float4 f1 = (att[u] < 0.f) ? f1b : f1a;
                float att2 = att[u] * att[u];
                float4 o;
                o.x = fmaf(att[u], f1.x, att2 * a01.x);
                o.y = fmaf(att[u], f1.y, att2 * a01.y);
                o.z = fmaf(att[u], f1.z, att2 * a23.x);
                o.w = fmaf(att[u], f1.w, att2 * a23.y);
                __stcs((float4*)out + (size_t)nn[u] * 32 + lane, o);
            }
        }
        a_pref = a_next;
    }
}

// ---------------- launch ----------------
extern "C" void kernel_launch(void* const* d_in, const int* in_sizes, int n_in,
                              void* d_out, int out_size) {
    const float* oh  = (const float*)d_in[0];
    const float* psi = (const float*)d_in[1];
    const float* Wq  = (const float*)d_in[2];
    const float* Wk  = (const float*)d_in[3];
    const float* Wv  = (const float*)d_in[4];
    const float* W1  = (const float*)d_in[5];
    const float* W2  = (const float*)d_in[6];
    const int*   bs  = (const int*)d_in[7];
    int N = in_sizes[7];
    int G = in_sizes[1];
    float* out = (float*)d_out;

    const int tab_smem = (FDIM * WPITCH + 2 * FDIM + 16 * FDIM) * 4;   // ~77 KB
    cudaFuncSetAttribute(k_scantab, cudaFuncAttributeMaxDynamicSharedMemorySize, tab_smem);

    int nvec = (N * EDIM) / 4;                // N*118 divisible by 4

    k_prep<<<1, 256>>>(Wq, Wk, psi, G);
    k_scantab<<<NTABBLK + NSCANBLK, 512, tab_smem>>>(
        (const float4*)oh, psi, bs, nvec, Wv, W1, W2);
    k_out<<<1184, 256>>>(psi, bs, out, N);
}

// round 15
// speedup vs baseline: 1.4478x; 1.4478x over previous
#include <cuda_runtime.h>
#include <cuda_fp16.h>
#include <cstdint>
#include <math.h>

#define NMAX 262144
#define GMAX 8192
#define EDIM 118
#define FDIM 128
#define KTAB 512          // intervals per branch (KTAB+1 grid rows)
#define WPITCH 132        // 16B-aligned rows; conflict-free LDS.128 phases

// ---------------- scratch (device globals; no allocation) ----------------
__device__ float  g_y[NMAX];
__device__ float  g_att[NMAX];
__device__ float  g_denom[GMAX];
__device__ float  g_dot[EDIM * 2];
__device__ float  g_amax;
__device__ float  g_lin[2 * FDIM];                   // F'(0) per branch
__device__ __half g_tabh[2][KTAB + 1][FDIM];         // residual G(|att|), fp16 rows (256B)

// ---------------- helpers ----------------
__device__ __forceinline__ float s1f(float x) {      // silu(x) - x/2, O(x^2), no cancellation
    return 0.5f * x * tanhf(0.5f * x);
}
__device__ __forceinline__ float dot128v(const float* __restrict__ a,
                                         const float* __restrict__ b) {
    float d0 = 0.f, d1 = 0.f, d2 = 0.f, d3 = 0.f;
#pragma unroll
    for (int k = 0; k < FDIM; k += 8) {
        float4 av0 = *(const float4*)(a + k);
        float4 bv0 = *(const float4*)(b + k);
        float4 av1 = *(const float4*)(a + k + 4);
        float4 bv1 = *(const float4*)(b + k + 4);
        d0 = fmaf(av0.x, bv0.x, d0);
        d1 = fmaf(av0.y, bv0.y, d1);
        d2 = fmaf(av0.z, bv0.z, d2);
        d3 = fmaf(av0.w, bv0.w, d3);
        d0 = fmaf(av1.x, bv1.x, d0);
        d1 = fmaf(av1.y, bv1.y, d1);
        d2 = fmaf(av1.z, bv1.z, d2);
        d3 = fmaf(av1.w, bv1.w, d3);
    }
    return (d0 + d1) + (d2 + d3);
}

// ---------------- kernel: parallel prep (zero denom | amax | dot table) -------
// blocks 0..31   : zero g_denom
// block  32      : amax over psi
// blocks 33..150 : dot table, one element per block
__global__ void __launch_bounds__(256)
k_prep(const float* __restrict__ Wq, const float* __restrict__ Wk,
       const float* __restrict__ psi, int G) {
    int b = blockIdx.x;
    int t = threadIdx.x;
    if (b < 32) {
        int i = b * 256 + t;
        if (i < G) g_denom[i] = 0.f;
        return;
    }
    if (b == 32) {
        __shared__ float smax[8];
        float m = 0.f;
        const float4* p4 = (const float4*)psi;
        int nv = G / 4;
#pragma unroll 8
        for (int i = t; i < nv; i += 256) {
            float4 v = p4[i];
            m = fmaxf(m, fmaxf(fmaxf(fabsf(v.x), fabsf(v.y)),
                               fmaxf(fabsf(v.z), fabsf(v.w))));
        }
#pragma unroll
        for (int o = 16; o; o >>= 1) m = fmaxf(m, __shfl_xor_sync(0xffffffffu, m, o));
        if ((t & 31) == 0) smax[t >> 5] = m;
        __syncthreads();
        if (t == 0) {
            float mm = 1e-12f;
            for (int i = 0; i < 8; ++i) mm = fmaxf(mm, smax[i]);
            g_amax = mm;
        }
        return;
    }
    // dot-table block: element e
    int e = b - 33;                        // 0..117
    __shared__ float sk[256];
    __shared__ float sp0[4], sp1[4];
    sk[t] = Wk[t];
    __syncthreads();
    float p0 = 0.f, p1 = 0.f;
    if (t < 128) {
        float w = Wq[t * EDIM + e];
        p0 = w * sk[t];
        p1 = w * sk[128 + t];
    }
#pragma unroll
    for (int o = 16; o; o >>= 1) {
        p0 += __shfl_xor_sync(0xffffffffu, p0, o);
        p1 += __shfl_xor_sync(0xffffffffu, p1, o);
    }
    if (t < 128 && (t & 31) == 0) {
        sp0[t >> 5] = p0;
        sp1[t >> 5] = p1;
    }
    __syncthreads();
    if (t == 0) {
        g_dot[e * 2 + 0] = (sp0[0] + sp0[1]) + (sp0[2] + sp0[3]);
        g_dot[e * 2 + 1] = (sp1[0] + sp1[1]) + (sp1[2] + sp1[3]);
    }
}

// ---------------- kernel: grid-stride flat scan (4x float4 ILP) ---------------
__global__ void __launch_bounds__(512)
k_scan(const float4* __restrict__ oh4, const float* __restrict__ psi,
       const int* __restrict__ bs, int nvec) {
    int stride = gridDim.x * blockDim.x;
    for (int base = blockIdx.x * blockDim.x + threadIdx.x; base < nvec; base += 4 * stride) {
        float4 v[4];
        int ii[4];
#pragma unroll
        for (int u = 0; u < 4; ++u) {
            ii[u] = base + u * stride;
            if (ii[u] < nvec) v[u] = __ldcs(oh4 + ii[u]);
            else v[u] = make_float4(0.f, 0.f, 0.f, 0.f);
        }
#pragma unroll
        for (int u = 0; u < 4; ++u) {
            float vv[4] = {v[u].x, v[u].y, v[u].z, v[u].w};
#pragma unroll
            for (int c = 0; c < 4; ++c) {
                if (vv[c] != 0.f) {
                    unsigned f = 4u * (unsigned)ii[u] + (unsigned)c;
                    unsigned atom = f / 118u;
                    unsigned e = f - atom * 118u;
                    int g = bs[atom];
                    float p = psi[g];
                    int r = (p < 0.f) ? 1 : 0;
                    float qk = g_dot[e * 2 + r] * 0.08838834764831845f;  // 1/sqrt(128)
                    float y = (qk > 20.f) ? qk : log1pf(expf(qk));
                    g_y[atom] = y;
                    atomicAdd(&g_denom[g], y);
                }
            }
        }
    }
}

// ---------------- kernel: two-phase residual table + F'(0), LDS.128 -----------
//   hlin = W1@wv;  h(a) = 0.5a*hlin + W1@s1(a*wv)
//   F(a) - a*F1 = W2 @ [ 0.5*(W1@s1(a*wv)) + s1(h(a)) ];  F1 = wv + 0.25*(W2@hlin)
// grid: 130 blocks = 2 branches x 65 groups of 8 nodes; 128 threads
__global__ void k_tab(const float* __restrict__ Wv, const float* __restrict__ W1,
                      const float* __restrict__ W2) {
    extern __shared__ float sm[];
    float* sW  = sm;                       // [128][WPITCH] (W1, then W2)
    float* swv = sW + FDIM * WPITCH;       // [128]
    float* shl = swv + FDIM;               // [128] hlin
    float* sSv = shl + FDIM;               // [8][128] s1(a_u*wv)
    float* sB  = sSv + 8 * FDIM;           // [8][128] bracket
    int t = threadIdx.x;
    int b = blockIdx.x;
    int r = (b >= 65) ? 1 : 0;
    int i0 = (b - r * 65) * 8;
    float sgn = r ? -1.f : 1.f;

    const float4* W1v = (const float4*)W1;
    for (int i = t; i < FDIM * 32; i += 128) {
        int row = i >> 5, c = (i & 31) * 4;
        *(float4*)(sW + row * WPITCH + c) = W1v[i];
    }
    float wv = Wv[r * FDIM + t];
    swv[t] = wv;
    __syncthreads();

    const float* wrow = sW + t * WPITCH;
    float hlin = dot128v(wrow, swv);
    shl[t] = hlin;

    float amax = g_amax;
    float av[8];
#pragma unroll
    for (int u = 0; u < 8; ++u) {
        int i = i0 + u;
        float mag = (i == 0) ? (amax * (1.f / 8192.f)) : (amax * (float)i * (1.f / KTAB));
        av[u] = sgn * mag;
        sSv[u * FDIM + t] = s1f(av[u] * wv);
    }
    __syncthreads();

#pragma unroll
    for (int u = 0; u < 8; ++u) {
        if (i0 + u > KTAB) break;
        float tt = dot128v(wrow, sSv + u * FDIM);   // W1@s1(a*wv)
        float h = fmaf(0.5f * av[u], hlin, tt);
        sB[u * FDIM + t] = fmaf(0.5f, tt, s1f(h));
    }
    __syncthreads();

    const float4* W2v = (const float4*)W2;
    for (int i = t; i < FDIM * 32; i += 128) {
        int row = i >> 5, c = (i & 31) * 4;
        *(float4*)(sW + row * WPITCH + c) = W2v[i];
    }
    __syncthreads();

    if (i0 == 0) {
        float gl = dot128v(wrow, shl);
        g_lin[r * FDIM + t] = fmaf(0.25f, gl, wv);
    }
#pragma unroll
    for (int u = 0; u < 8; ++u) {
        int i = i0 + u;
        if (i > KTAB) break;
        float resid = dot128v(wrow, sB + u * FDIM);
        g_tabh[r][i][t] = __float2half(resid / (av[u] * av[u]));
    }
}

// ---------------- kernel: per-atom attention scalar ---------------------------
__global__ void __launch_bounds__(256)
k_att(const float* __restrict__ psi, const int* __restrict__ bs, int N) {
    int n = blockIdx.x * blockDim.x + threadIdx.x;
    if (n >= N) return;
    int g = bs[n];
    float p = psi[g];
    g_att[n] = p * g_y[n] / (g_denom[g] + 1e-6f);
}

// ---------------- kernel: persistent warp-per-atom lookup + epilogue ----------
__global__ void __launch_bounds__(256)
k_out(float* __restrict__ out, int N) {
    int lane = threadIdx.x & 31;
    int gw = (blockIdx.x * blockDim.x + threadIdx.x) >> 5;
    int nwarps = (gridDim.x * blockDim.x) >> 5;
    // F1 for both branches in registers, loaded once per thread
    float4 f1a = ((const float4*)g_lin)[lane];
    float4 f1b = ((const float4*)(g_lin + FDIM))[lane];
    float scale = (float)KTAB / g_amax;

    for (int n0 = gw; n0 < N; n0 += 4 * nwarps) {
        int nn[4];
        float att[4];
        uint2 raw[4];
#pragma unroll
        for (int u = 0; u < 4; ++u) {
            nn[u] = n0 + u * nwarps;
            att[u] = (nn[u] < N) ? g_att[nn[u]] : 0.f;
        }
#pragma unroll
        for (int u = 0; u < 4; ++u) {
            int r = (att[u] < 0.f) ? 1 : 0;
            int j = __float2int_rn(fabsf(att[u]) * scale);
            if (j > KTAB) j = KTAB;
            raw[u] = (nn[u] < N) ? __ldg((const uint2*)(&g_tabh[r][j][0]) + lane)
                                 : make_uint2(0u, 0u);
        }
#pragma unroll
        for (int u = 0; u < 4; ++u) {
            if (nn[u] < N) {
                float2 a01 = __half22float2(*(const __half2*)&raw[u].x);
                float2 a23 = __half22float2(*(const __half2*)&raw[u].y);
                float4 f1 = (att[u] < 0.f) ? f1b : f1a;
                float att2 = att[u] * att[u];
                float4 o;
                o.x = fmaf(att[u], f1.x, att2 * a01.x);
                o.y = fmaf(att[u], f1.y, att2 * a01.y);
                o.z = fmaf(att[u], f1.z, att2 * a23.x);
                o.w = fmaf(att[u], f1.w, att2 * a23.y);
                __stcs((float4*)out + (size_t)nn[u] * 32 + lane, o);
            }
        }
    }
}

// ---------------- launch ----------------
extern "C" void kernel_launch(void* const* d_in, const int* in_sizes, int n_in,
                              void* d_out, int out_size) {
    const float* oh  = (const float*)d_in[0];
    const float* psi = (const float*)d_in[1];
    const float* Wq  = (const float*)d_in[2];
    const float* Wk  = (const float*)d_in[3];
    const float* Wv  = (const float*)d_in[4];
    const float* W1  = (const float*)d_in[5];
    const float* W2  = (const float*)d_in[6];
    const int*   bs  = (const int*)d_in[7];
    int N = in_sizes[7];
    int G = in_sizes[1];
    float* out = (float*)d_out;

    const int tab_smem = (FDIM * WPITCH + 2 * FDIM + 16 * FDIM) * 4;   // ~77 KB
    cudaFuncSetAttribute(k_tab, cudaFuncAttributeMaxDynamicSharedMemorySize, tab_smem);

    int nvec = (N * EDIM) / 4;                // N*118 divisible by 4

    k_prep<<<151, 256>>>(Wq, Wk, psi, G);
    k_scan<<<592, 512>>>((const float4*)oh, psi, bs, nvec);
    k_tab<<<130, 128, tab_smem>>>(Wv, W1, W2);
    k_att<<<(N + 255) / 256, 256>>>(psi, bs, N);
    k_out<<<1184, 256>>>(out, N);
}

// round 16
// speedup vs baseline: 1.4813x; 1.0231x over previous
#include <cuda_runtime.h>
#include <cuda_fp16.h>
#include <cstdint>
#include <math.h>

#define NMAX 262144
#define GMAX 8192
#define EDIM 118
#define FDIM 128
#define KTAB 512          // intervals per branch (KTAB+1 grid rows)
#define WPITCH 132        // 16B-aligned rows; conflict-free LDS.128 phases
#define NNODE 4           // nodes per tab block

// ---------------- scratch (device globals; no allocation) ----------------
__device__ float  g_y[NMAX];
__device__ float  g_denom[GMAX];
__device__ float  g_dot[EDIM * 2];
__device__ float  g_amax;
__device__ float  g_lin[2 * FDIM];                   // F'(0) per branch
__device__ __half g_tabh[2][KTAB + 1][FDIM];         // residual G(|att|), fp16 rows (256B)

// ---------------- helpers ----------------
__device__ __forceinline__ float s1f(float x) {      // silu(x) - x/2, O(x^2), no cancellation
    return 0.5f * x * tanhf(0.5f * x);
}
__device__ __forceinline__ float dot128v(const float* __restrict__ a,
                                         const float* __restrict__ b) {
    float d0 = 0.f, d1 = 0.f, d2 = 0.f, d3 = 0.f;
#pragma unroll
    for (int k = 0; k < FDIM; k += 8) {
        float4 av0 = *(const float4*)(a + k);
        float4 bv0 = *(const float4*)(b + k);
        float4 av1 = *(const float4*)(a + k + 4);
        float4 bv1 = *(const float4*)(b + k + 4);
        d0 = fmaf(av0.x, bv0.x, d0);
        d1 = fmaf(av0.y, bv0.y, d1);
        d2 = fmaf(av0.z, bv0.z, d2);
        d3 = fmaf(av0.w, bv0.w, d3);
        d0 = fmaf(av1.x, bv1.x, d0);
        d1 = fmaf(av1.y, bv1.y, d1);
        d2 = fmaf(av1.z, bv1.z, d2);
        d3 = fmaf(av1.w, bv1.w, d3);
    }
    return (d0 + d1) + (d2 + d3);
}

// ---------------- kernel: parallel prep (zero denom | amax | dot table) -------
__global__ void __launch_bounds__(256)
k_prep(const float* __restrict__ Wq, const float* __restrict__ Wk,
       const float* __restrict__ psi, int G) {
    int b = blockIdx.x;
    int t = threadIdx.x;
    if (b < 32) {
        int i = b * 256 + t;
        if (i < G) g_denom[i] = 0.f;
        return;
    }
    if (b == 32) {
        __shared__ float smax[8];
        float m = 0.f;
        const float4* p4 = (const float4*)psi;
        int nv = G / 4;
#pragma unroll 8
        for (int i = t; i < nv; i += 256) {
            float4 v = p4[i];
            m = fmaxf(m, fmaxf(fmaxf(fabsf(v.x), fabsf(v.y)),
                               fmaxf(fabsf(v.z), fabsf(v.w))));
        }
#pragma unroll
        for (int o = 16; o; o >>= 1) m = fmaxf(m, __shfl_xor_sync(0xffffffffu, m, o));
        if ((t & 31) == 0) smax[t >> 5] = m;
        __syncthreads();
        if (t == 0) {
            float mm = 1e-12f;
            for (int i = 0; i < 8; ++i) mm = fmaxf(mm, smax[i]);
            g_amax = mm;
        }
        return;
    }
    // dot-table block: element e
    int e = b - 33;                        // 0..117
    __shared__ float sk[256];
    __shared__ float sp0[4], sp1[4];
    sk[t] = Wk[t];
    __syncthreads();
    float p0 = 0.f, p1 = 0.f;
    if (t < 128) {
        float w = Wq[t * EDIM + e];
        p0 = w * sk[t];
        p1 = w * sk[128 + t];
    }
#pragma unroll
    for (int o = 16; o; o >>= 1) {
        p0 += __shfl_xor_sync(0xffffffffu, p0, o);
        p1 += __shfl_xor_sync(0xffffffffu, p1, o);
    }
    if (t < 128 && (t & 31) == 0) {
        sp0[t >> 5] = p0;
        sp1[t >> 5] = p1;
    }
    __syncthreads();
    if (t == 0) {
        g_dot[e * 2 + 0] = (sp0[0] + sp0[1]) + (sp0[2] + sp0[3]);
        g_dot[e * 2 + 1] = (sp1[0] + sp1[1]) + (sp1[2] + sp1[3]);
    }
}

// ---------------- kernel: grid-stride flat scan (4x float4 ILP) ---------------
__global__ void __launch_bounds__(512)
k_scan(const float4* __restrict__ oh4, const float* __restrict__ psi,
       const int* __restrict__ bs, int nvec) {
    int stride = gridDim.x * blockDim.x;
    for (int base = blockIdx.x * blockDim.x + threadIdx.x; base < nvec; base += 4 * stride) {
        float4 v[4];
        int ii[4];
#pragma unroll
        for (int u = 0; u < 4; ++u) {
            ii[u] = base + u * stride;
            if (ii[u] < nvec) v[u] = __ldcs(oh4 + ii[u]);
            else v[u] = make_float4(0.f, 0.f, 0.f, 0.f);
        }
#pragma unroll
        for (int u = 0; u < 4; ++u) {
            float vv[4] = {v[u].x, v[u].y, v[u].z, v[u].w};
#pragma unroll
            for (int c = 0; c < 4; ++c) {
                if (vv[c] != 0.f) {
                    unsigned f = 4u * (unsigned)ii[u] + (unsigned)c;
                    unsigned atom = f / 118u;
                    unsigned e = f - atom * 118u;
                    int g = bs[atom];
                    float p = psi[g];
                    int r = (p < 0.f) ? 1 : 0;
                    float qk = g_dot[e * 2 + r] * 0.08838834764831845f;  // 1/sqrt(128)
                    float y = (qk > 20.f) ? qk : log1pf(expf(qk));
                    g_y[atom] = y;
                    atomicAdd(&g_denom[g], y);
                }
            }
        }
    }
}

// ---------------- kernel: two-phase residual table + F'(0), LDS.128 -----------
//   hlin = W1@wv;  h(a) = 0.5a*hlin + W1@s1(a*wv)
//   F(a) - a*F1 = W2 @ [ 0.5*(W1@s1(a*wv)) + s1(h(a)) ];  F1 = wv + 0.25*(W2@hlin)
// grid: 258 blocks = 2 branches x 129 groups of NNODE=4 nodes; 128 threads
__global__ void k_tab(const float* __restrict__ Wv, const float* __restrict__ W1,
                      const float* __restrict__ W2) {
    extern __shared__ float sm[];
    float* sW  = sm;                       // [128][WPITCH] (W1, then W2)
    float* swv = sW + FDIM * WPITCH;       // [128]
    float* shl = swv + FDIM;               // [128] hlin
    float* sSv = shl + FDIM;               // [NNODE][128] s1(a_u*wv)
    float* sB  = sSv + NNODE * FDIM;       // [NNODE][128] bracket
    int t = threadIdx.x;
    int b = blockIdx.x;
    int r = (b >= 129) ? 1 : 0;
    int i0 = (b - r * 129) * NNODE;
    float sgn = r ? -1.f : 1.f;

    const float4* W1v = (const float4*)W1;
    for (int i = t; i < FDIM * 32; i += 128) {
        int row = i >> 5, c = (i & 31) * 4;
        *(float4*)(sW + row * WPITCH + c) = W1v[i];
    }
    float wv = Wv[r * FDIM + t];
    swv[t] = wv;
    __syncthreads();

    const float* wrow = sW + t * WPITCH;
    float hlin = dot128v(wrow, swv);
    shl[t] = hlin;

    float amax = g_amax;
    float av[NNODE];
#pragma unroll
    for (int u = 0; u < NNODE; ++u) {
        int i = i0 + u;
        float mag = (i == 0) ? (amax * (1.f / 8192.f)) : (amax * (float)i * (1.f / KTAB));
        av[u] = sgn * mag;
        sSv[u * FDIM + t] = s1f(av[u] * wv);
    }
    __syncthreads();

#pragma unroll
    for (int u = 0; u < NNODE; ++u) {
        if (i0 + u > KTAB) break;
        float tt = dot128v(wrow, sSv + u * FDIM);   // W1@s1(a*wv)
        float h = fmaf(0.5f * av[u], hlin, tt);
        sB[u * FDIM + t] = fmaf(0.5f, tt, s1f(h));
    }
    __syncthreads();

    const float4* W2v = (const float4*)W2;
    for (int i = t; i < FDIM * 32; i += 128) {
        int row = i >> 5, c = (i & 31) * 4;
        *(float4*)(sW + row * WPITCH + c) = W2v[i];
    }
    __syncthreads();

    if (i0 == 0) {
        float gl = dot128v(wrow, shl);
        g_lin[r * FDIM + t] = fmaf(0.25f, gl, wv);
    }
#pragma unroll
    for (int u = 0; u < NNODE; ++u) {
        int i = i0 + u;
        if (i > KTAB) break;
        float resid = dot128v(wrow, sB + u * FDIM);
        g_tabh[r][i][t] = __float2half(resid / (av[u] * av[u]));
    }
}

// ---------------- kernel: persistent fused att + lookup + epilogue ------------
__device__ __forceinline__ float att_gather(const float* __restrict__ psi,
                                            const int* __restrict__ bs,
                                            int n0, int nwarps, int lane, int N) {
    float a = 0.f;
    if (lane < 4) {
        int n = n0 + lane * nwarps;
        if (n < N) {
            int g = __ldg(bs + n);
            float p = __ldg(psi + g);
            a = p * g_y[n] / (g_denom[g] + 1e-6f);
        }
    }
    return a;
}

__global__ void __launch_bounds__(256)
k_out(const float* __restrict__ psi, const int* __restrict__ bs,
      float* __restrict__ out, int N) {
    int lane = threadIdx.x & 31;
    int gw = (blockIdx.x * blockDim.x + threadIdx.x) >> 5;
    int nwarps = (gridDim.x * blockDim.x) >> 5;
    int step = 4 * nwarps;
    // F1 for both branches in registers, loaded once per thread
    float4 f1a = ((const float4*)g_lin)[lane];
    float4 f1b = ((const float4*)(g_lin + FDIM))[lane];
    float scale = (float)KTAB / g_amax;

    float a_pref = att_gather(psi, bs, gw, nwarps, lane, N);

    for (int n0 = gw; n0 < N; n0 += step) {
        float att[4];
#pragma unroll
        for (int u = 0; u < 4; ++u)
            att[u] = __shfl_sync(0xffffffffu, a_pref, u);
        // prefetch next chunk's att (loads overlap current processing)
        float a_next = att_gather(psi, bs, n0 + step, nwarps, lane, N);

        uint2 raw[4];
        int nn[4];
#pragma unroll
        for (int u = 0; u < 4; ++u) {
            nn[u] = n0 + u * nwarps;
            int r = (att[u] < 0.f) ? 1 : 0;
            int j = __float2int_rn(fabsf(att[u]) * scale);
            if (j > KTAB) j = KTAB;
            raw[u] = (nn[u] < N) ? __ldg((const uint2*)(&g_tabh[r][j][0]) + lane)
                                 : make_uint2(0u, 0u);
        }
#pragma unroll
        for (int u = 0; u < 4; ++u) {
            if (nn[u] < N) {
                float2 a01 = __half22float2(*(const __half2*)&raw[u].x);
                float2 a23 = __half22float2(*(const __half2*)&raw[u].y);
                float4 f1 = (att[u] < 0.f) ? f1b : f1a;
                float att2 = att[u] * att[u];
                float4 o;
                o.x = fmaf(att[u], f1.x, att2 * a01.x);
                o.y = fmaf(att[u], f1.y, att2 * a01.y);
                o.z = fmaf(att[u], f1.z, att2 * a23.x);
                o.w = fmaf(att[u], f1.w, att2 * a23.y);
                __stcs((float4*)out + (size_t)nn[u] * 32 + lane, o);
            }
        }
        a_pref = a_next;
    }
}

// ---------------- launch ----------------
extern "C" void kernel_launch(void* const* d_in, const int* in_sizes, int n_in,
                              void* d_out, int out_size) {
    const float* oh  = (const float*)d_in[0];
    const float* psi = (const float*)d_in[1];
    const float* Wq  = (const float*)d_in[2];
    const float* Wk  = (const float*)d_in[3];
    const float* Wv  = (const float*)d_in[4];
    const float* W1  = (const float*)d_in[5];
    const float* W2  = (const float*)d_in[6];
    const int*   bs  = (const int*)d_in[7];
    int N = in_sizes[7];
    int G = in_sizes[1];
    float* out = (float*)d_out;

    const int tab_smem = (FDIM * WPITCH + 2 * FDIM + 2 * NNODE * FDIM) * 4;  // ~73 KB
    cudaFuncSetAttribute(k_tab, cudaFuncAttributeMaxDynamicSharedMemorySize, tab_smem);

    int nvec = (N * EDIM) / 4;                // N*118 divisible by 4

    k_prep<<<151, 256>>>(Wq, Wk, psi, G);
    k_scan<<<592, 512>>>((const float4*)oh, psi, bs, nvec);
    k_tab<<<258, 128, tab_smem>>>(Wv, W1, W2);
    k_out<<<1184, 256>>>(psi, bs, out, N);
}